// round 14
// baseline (speedup 1.0000x reference)
#include <cuda_runtime.h>
#include <cstdint>

#define EMB 128
#define ASTRIDE 132
#define TROWS 64
#define MAXNODES 100000
#define MAXEDGES 1048576

// Scratch (device globals: no allocations allowed in kernel_launch)
__device__ __align__(128) float g_Lp[MAXNODES * EMB];
__device__ __align__(128) float g_Rp[MAXNODES * EMB];
__device__ __align__(128) float g_acc[MAXNODES * EMB];
__device__ __align__(128) int g_cnt[MAXNODES];        // counts, then fill offsets
__device__ __align__(128) int g_rowptr[MAXNODES + 1];
__device__ __align__(128) int g_elist[MAXEDGES];
__device__ __align__(128) float g_Wc[EMB * EMB];     // sp * (W1a @ Wf)
__device__ __align__(128) float g_bvec[EMB];         // sp * (W1a @ bf)
// fragment-packed hi-only tf32 weights: [m][(ks*16+nt)*32+lane] = {b0h,b1h}
// m: 0=W_left 1=W_right 2=Wc 3=W1b 4=W_out2
__device__ __align__(128) float2 g_frag[5][8192];
__device__ int g_is64;

// ---------------- helpers ----------------
__device__ __forceinline__ uint32_t tf32r(float v) {
    uint32_t r;
    asm("cvt.rna.tf32.f32 %0, %1;" : "=r"(r) : "f"(v));
    return r;
}
__device__ __forceinline__ void mma8(float* c, uint32_t a0, uint32_t a1,
                                     uint32_t a2, uint32_t a3,
                                     uint32_t b0, uint32_t b1) {
    asm volatile(
        "mma.sync.aligned.m16n8k8.row.col.f32.tf32.tf32.f32 "
        "{%0,%1,%2,%3}, {%4,%5,%6,%7}, {%8,%9}, {%0,%1,%2,%3};"
        : "+f"(c[0]), "+f"(c[1]), "+f"(c[2]), "+f"(c[3])
        : "r"(a0), "r"(a1), "r"(a2), "r"(a3), "r"(b0), "r"(b1));
}

// ---------------------------------------------------------------------------
// 64x128x128 2-pass compensated-TF32 GEMM (D = Ah@Bh + Al@Bh), 8 warps.
// ---------------------------------------------------------------------------
__device__ __forceinline__ void gemm64(const float* __restrict__ As,
                                       const float2* __restrict__ Bf,
                                       float acc[8][4], int rg, int ch, int lane) {
    const int g = lane >> 2, t = lane & 3;
    const float* r0 = As + (rg * 16 + g) * ASTRIDE;
    const float* r8 = r0 + 8 * ASTRIDE;
#pragma unroll
    for (int ks = 0; ks < 16; ks++) {
        const int k = ks * 8 + t;
        const float a0 = r0[k], a1 = r8[k], a2 = r0[k + 4], a3 = r8[k + 4];
        const uint32_t a0h = tf32r(a0), a1h = tf32r(a1);
        const uint32_t a2h = tf32r(a2), a3h = tf32r(a3);
        const uint32_t a0l = tf32r(a0 - __uint_as_float(a0h));
        const uint32_t a1l = tf32r(a1 - __uint_as_float(a1h));
        const uint32_t a2l = tf32r(a2 - __uint_as_float(a2h));
        const uint32_t a3l = tf32r(a3 - __uint_as_float(a3h));
        const float2* bp = Bf + ks * 512 + ch * 256 + lane;
#pragma unroll
        for (int nt = 0; nt < 8; nt++) {
            const float2 b = bp[nt * 32];
            const uint32_t b0h = __float_as_uint(b.x), b1h = __float_as_uint(b.y);
            mma8(acc[nt], a0h, a1h, a2h, a3h, b0h, b1h);
            mma8(acc[nt], a0l, a1l, a2l, a3l, b0h, b1h);
        }
    }
}

// stage TROWS rows of a row-major [n, 128] matrix into padded smem (zero-fill OOB)
__device__ __forceinline__ void stage_rows(const float* __restrict__ gptr, int row0,
                                           int n, float* As, int tid) {
    for (int i = tid; i < TROWS * 32; i += 256) {
        const int r = i >> 5, c4 = i & 31;
        float4 v = make_float4(0.f, 0.f, 0.f, 0.f);
        if (row0 + r < n)
            v = ((const float4*)(gptr + (size_t)(row0 + r) * EMB))[c4];
        *(float4*)(As + r * ASTRIDE + c4 * 4) = v;
    }
}

// ---------------------------------------------------------------------------
// prep1: detect idx width; zero g_cnt (FULL n_right range — must be re-zeroed
// every call for graph replay idempotence); Wc = sp*(W1a@Wf); bvec = sp*(W1a@bf).
// ---------------------------------------------------------------------------
__global__ void prep1_kernel(const float* __restrict__ Wf, const float* __restrict__ W1,
                             const float* __restrict__ bf, const float* __restrict__ sp_p,
                             const long long* __restrict__ eidx, int n_edges,
                             int n_right) {
    const int idx = blockIdx.x * blockDim.x + threadIdx.x;
    if (idx == 0) {
        int m = n_edges < 64 ? n_edges : 64;
        int ok = 1;
        for (int i = 0; i < m; i++) {
            long long v = eidx[i];
            if (v < 0 || v >= (1LL << 31)) { ok = 0; break; }
        }
        g_is64 = ok;
    }
    if (idx < n_right) g_cnt[idx] = 0;
    if (idx < EMB * EMB) {
        const int j = idx >> 7, k = idx & 127;
        float s = 0.f;
        for (int m = 0; m < EMB; m++)
            s = fmaf(W1[j * 2 * EMB + m], Wf[m * EMB + k], s);
        g_Wc[idx] = s * sp_p[0];
    }
    if (idx < EMB) {
        float s = 0.f;
        for (int m = 0; m < EMB; m++)
            s = fmaf(W1[idx * 2 * EMB + m], bf[m], s);
        g_bvec[idx] = s * sp_p[0];
    }
}

// ---------------------------------------------------------------------------
// prep2: pack fragment-ordered hi tf32 weights.
// ---------------------------------------------------------------------------
__global__ void prep2_kernel(const float* __restrict__ Wl, const float* __restrict__ Wr,
                             const float* __restrict__ W1, const float* __restrict__ W2) {
    const int idx = blockIdx.x * blockDim.x + threadIdx.x;
    if (idx >= 5 * 8192) return;
    const int m = idx >> 13, r = idx & 8191;
    const int lane = r & 31, nt = (r >> 5) & 15, ks = r >> 9;   // ks in [0,16)
    const int g = lane >> 2, t = lane & 3;
    const int n = nt * 8 + g, k0 = ks * 8 + t;

    const float* src; int L, off;
    switch (m) {
        case 0:  src = Wl;   L = EMB;     off = 0;   break;
        case 1:  src = Wr;   L = EMB;     off = 0;   break;
        case 2:  src = g_Wc; L = EMB;     off = 0;   break;
        case 3:  src = W1;   L = 2 * EMB; off = EMB; break;
        default: src = W2;   L = EMB;     off = 0;   break;
    }
    const float v0 = src[n * L + off + k0];
    const float v1 = src[n * L + off + k0 + 4];
    g_frag[m][r] = make_float2(__uint_as_float(tf32r(v0)),
                               __uint_as_float(tf32r(v1)));
}

// ---------------------------------------------------------------------------
// CSR build: histogram -> scan -> scatter
// ---------------------------------------------------------------------------
__global__ void hist_kernel(const void* __restrict__ eidx_raw, int n_edges) {
    const int e = blockIdx.x * blockDim.x + threadIdx.x;
    if (e >= n_edges) return;
    const int d = g_is64 ? (int)((const long long*)eidx_raw)[n_edges + e]
                         : ((const int*)eidx_raw)[n_edges + e];
    atomicAdd(&g_cnt[d], 1);
}

__global__ void scan_kernel(int n_right) {
    __shared__ int part[1024];
    const int tid = threadIdx.x;
    const int chunk = (n_right + 1023) / 1024;
    const int beg = tid * chunk;
    const int end = min(beg + chunk, n_right);

    int s = 0;
    for (int i = beg; i < end; i++) s += g_cnt[i];
    part[tid] = s;
    __syncthreads();
    // inclusive Hillis-Steele scan
    for (int ofs = 1; ofs < 1024; ofs <<= 1) {
        int v = part[tid];
        int add = (tid >= ofs) ? part[tid - ofs] : 0;
        __syncthreads();
        part[tid] = v + add;
        __syncthreads();
    }
    int off = (tid == 0) ? 0 : part[tid - 1];
    for (int i = beg; i < end; i++) {
        const int c = g_cnt[i];
        g_rowptr[i] = off;
        g_cnt[i] = off;   // becomes fill cursor
        off += c;
    }
    if (tid == 1023) g_rowptr[n_right] = off;
}

__global__ void scatter_kernel(const void* __restrict__ eidx_raw, int n_edges) {
    const int e = blockIdx.x * blockDim.x + threadIdx.x;
    if (e >= n_edges) return;
    const int d = g_is64 ? (int)((const long long*)eidx_raw)[n_edges + e]
                         : ((const int*)eidx_raw)[n_edges + e];
    const int pos = atomicAdd(&g_cnt[d], 1);
    g_elist[pos] = e;
}

// ---------------------------------------------------------------------------
// Tensor-core projections: Lp = left@WL^T + bL ; Rp = right@WR^T
// ---------------------------------------------------------------------------
__global__ __launch_bounds__(256) void proj_mma(
    const float* __restrict__ left, const float* __restrict__ right,
    const float* __restrict__ bL, int n_left, int n_right, int blocksL)
{
    extern __shared__ float sm[];
    float* As = sm;
    float* sBias = sm + TROWS * ASTRIDE;
    const int tid = threadIdx.x, warp = tid >> 5, lane = tid & 31;
    const int rg = warp >> 1, ch = warp & 1;

    const float* A; const float2* Bf; float* outp; int n, row0;
    if ((int)blockIdx.x < blocksL) {
        A = left;  Bf = g_frag[0]; outp = g_Lp; n = n_left;
        row0 = blockIdx.x * TROWS;
        if (tid < 128) sBias[tid] = bL[tid];
    } else {
        A = right; Bf = g_frag[1]; outp = g_Rp; n = n_right;
        row0 = (blockIdx.x - blocksL) * TROWS;
        if (tid < 128) sBias[tid] = 0.f;
    }
    stage_rows(A, row0, n, As, tid);
    __syncthreads();

    float acc[8][4];
#pragma unroll
    for (int nt = 0; nt < 8; nt++)
#pragma unroll
        for (int i = 0; i < 4; i++) acc[nt][i] = 0.f;

    gemm64(As, Bf, acc, rg, ch, lane);

    const int g = lane >> 2, t = lane & 3;
    const int r0 = row0 + rg * 16 + g, r1 = r0 + 8;
#pragma unroll
    for (int nt = 0; nt < 8; nt++) {
        const int c = (ch * 8 + nt) * 8 + 2 * t;
        if (r0 < n) {
            float2 o = make_float2(acc[nt][0] + sBias[c], acc[nt][1] + sBias[c + 1]);
            *(float2*)(outp + (size_t)r0 * EMB + c) = o;
        }
        if (r1 < n) {
            float2 o = make_float2(acc[nt][2] + sBias[c], acc[nt][3] + sBias[c + 1]);
            *(float2*)(outp + (size_t)r1 * EMB + c) = o;
        }
    }
}

// ---------------------------------------------------------------------------
// CSR edge stage: one warp per destination d. Rp[d] + accumulator live in
// registers; only Lp[s] is gathered (51 MB, L2-resident). Plain store to
// g_acc[d] — no float atomics, no zero-init needed.
// ---------------------------------------------------------------------------
__global__ __launch_bounds__(256) void edge_csr(
    const void* __restrict__ eidx_raw, const float* __restrict__ ef,
    const float* __restrict__ wedge, const float* __restrict__ scale_p,
    int n_edges, int n_right)
{
    const int warp = threadIdx.x >> 5, lane = threadIdx.x & 31;
    const int d = blockIdx.x * 8 + warp;
    if (d >= n_right) return;

    const int beg = g_rowptr[d];
    const int end = g_rowptr[d + 1];
    const float scale = scale_p[0];
    const float4 we = ((const float4*)wedge)[lane];
    const float4 r = ((const float4*)(g_Rp + (size_t)d * EMB))[lane];
    const int is64 = g_is64;
    const long long* __restrict__ e64 = (const long long*)eidx_raw;
    const int* __restrict__ e32 = (const int*)eidx_raw;

    float4 a = make_float4(0.f, 0.f, 0.f, 0.f);
    for (int p = beg; p < end; p++) {
        const int e = g_elist[p];
        const int s = is64 ? (int)e64[e] : e32[e];
        const float fe = ef[e];
        const float4 l = ((const float4*)(g_Lp + (size_t)s * EMB))[lane];
        a.x += fmaxf(fmaf(fe, we.x, l.x + r.x) * scale, 0.f);
        a.y += fmaxf(fmaf(fe, we.y, l.y + r.y) * scale, 0.f);
        a.z += fmaxf(fmaf(fe, we.z, l.z + r.z) * scale, 0.f);
        a.w += fmaxf(fmaf(fe, we.w, l.w + r.w) * scale, 0.f);
    }
    ((float4*)(g_acc + (size_t)d * EMB))[lane] = a;
}

// ---------------------------------------------------------------------------
// Fused output: u = relu(acc@Wc^T + deg*bvec + right@W1b^T + b1);
//               out = u@W2^T + b2.   (Wf folded into Wc; deg from rowptr.)
// ---------------------------------------------------------------------------
__global__ __launch_bounds__(256) void out_mma(
    const float* __restrict__ right, const float* __restrict__ b1,
    const float* __restrict__ b2, float* __restrict__ out, int n_right)
{
    extern __shared__ float sm[];
    float* As = sm;                          // acc tile, later u tile
    float* Rs = sm + TROWS * ASTRIDE;        // right tile
    float* sBv = sm + 2 * TROWS * ASTRIDE;
    float* sB1 = sBv + 128;
    float* sB2 = sB1 + 128;
    const int tid = threadIdx.x, warp = tid >> 5, lane = tid & 31;
    const int rg = warp >> 1, ch = warp & 1;
    const int row0 = blockIdx.x * TROWS;

    if (tid < 128) {
        sBv[tid] = g_bvec[tid];
        sB1[tid] = b1[tid];
        sB2[tid] = b2[tid];
    }
    stage_rows(g_acc, row0, n_right, As, tid);
    stage_rows(right, row0, n_right, Rs, tid);
    __syncthreads();

    float acc[8][4];
#pragma unroll
    for (int nt = 0; nt < 8; nt++)
#pragma unroll
        for (int i = 0; i < 4; i++) acc[nt][i] = 0.f;

    gemm64(As, g_frag[2], acc, rg, ch, lane);   // acc_tile @ Wc^T
    gemm64(Rs, g_frag[3], acc, rg, ch, lane);   // + right @ W1b^T

    const int g = lane >> 2, t = lane & 3;
    const int sr0 = rg * 16 + g, sr1 = sr0 + 8;
    float d0 = 0.f, d1 = 0.f;
    if (row0 + sr0 < n_right)
        d0 = (float)(g_rowptr[row0 + sr0 + 1] - g_rowptr[row0 + sr0]);
    if (row0 + sr1 < n_right)
        d1 = (float)(g_rowptr[row0 + sr1 + 1] - g_rowptr[row0 + sr1]);
    __syncthreads();   // everyone done reading As

    // u = relu(acc + deg*bvec + b1) -> As
#pragma unroll
    for (int nt = 0; nt < 8; nt++) {
        const int c = (ch * 8 + nt) * 8 + 2 * t;
        As[sr0 * ASTRIDE + c]     = fmaxf(acc[nt][0] + d0 * sBv[c]     + sB1[c],     0.f);
        As[sr0 * ASTRIDE + c + 1] = fmaxf(acc[nt][1] + d0 * sBv[c + 1] + sB1[c + 1], 0.f);
        As[sr1 * ASTRIDE + c]     = fmaxf(acc[nt][2] + d1 * sBv[c]     + sB1[c],     0.f);
        As[sr1 * ASTRIDE + c + 1] = fmaxf(acc[nt][3] + d1 * sBv[c + 1] + sB1[c + 1], 0.f);
    }
    __syncthreads();

    // u @ W2^T
#pragma unroll
    for (int nt = 0; nt < 8; nt++)
#pragma unroll
        for (int i = 0; i < 4; i++) acc[nt][i] = 0.f;

    gemm64(As, g_frag[4], acc, rg, ch, lane);

    const int r0g = row0 + sr0, r1g = row0 + sr1;
#pragma unroll
    for (int nt = 0; nt < 8; nt++) {
        const int c = (ch * 8 + nt) * 8 + 2 * t;
        if (r0g < n_right) {
            float2 o = make_float2(acc[nt][0] + sB2[c], acc[nt][1] + sB2[c + 1]);
            *(float2*)(out + (size_t)r0g * EMB + c) = o;
        }
        if (r1g < n_right) {
            float2 o = make_float2(acc[nt][2] + sB2[c], acc[nt][3] + sB2[c + 1]);
            *(float2*)(out + (size_t)r1g * EMB + c) = o;
        }
    }
}

// ---------------------------------------------------------------------------
extern "C" void kernel_launch(void* const* d_in, const int* in_sizes, int n_in,
                              void* d_out, int out_size)
{
    const float* left   = (const float*)d_in[0];
    const void*  eidx   = d_in[1];
    const float* ef     = (const float*)d_in[2];
    const float* right  = (const float*)d_in[3];
    // d_in[4] = scatter_out_size scalar (derived from right_features instead)
    const float* W_left      = (const float*)d_in[5];
    const float* b_left      = (const float*)d_in[6];
    const float* W_edge      = (const float*)d_in[7];
    const float* W_right     = (const float*)d_in[8];
    const float* scale_final = (const float*)d_in[9];
    const float* W_final     = (const float*)d_in[10];
    const float* b_final     = (const float*)d_in[11];
    const float* scale_post  = (const float*)d_in[12];
    const float* W_out1      = (const float*)d_in[13];
    const float* b_out1      = (const float*)d_in[14];
    const float* W_out2      = (const float*)d_in[15];
    const float* b_out2      = (const float*)d_in[16];

    const int n_left  = in_sizes[0] / EMB;
    const int n_edges = in_sizes[2];          // edge_features count (EDGE_FEAT=1)
    const int n_right = in_sizes[3] / EMB;

    const int SM_PROJ = (TROWS * ASTRIDE + 128) * (int)sizeof(float);
    const int SM_OUT  = (2 * TROWS * ASTRIDE + 3 * 128) * (int)sizeof(float);
    cudaFuncSetAttribute(proj_mma, cudaFuncAttributeMaxDynamicSharedMemorySize, SM_PROJ);
    cudaFuncSetAttribute(out_mma,  cudaFuncAttributeMaxDynamicSharedMemorySize, SM_OUT);

    const int eb = (n_edges + 255) / 256;

    // prep: idx width, zero counts (FULL range!), folded weights, fragments
    const int prep1_span = (n_right > EMB * EMB) ? n_right : EMB * EMB;
    prep1_kernel<<<(prep1_span + 255) / 256, 256>>>(W_final, W_out1, b_final,
                                                    scale_post,
                                                    (const long long*)eidx,
                                                    n_edges, n_right);
    prep2_kernel<<<(5 * 8192 + 255) / 256, 256>>>(W_left, W_right, W_out1, W_out2);

    // CSR build
    hist_kernel<<<eb, 256>>>(eidx, n_edges);
    scan_kernel<<<1, 1024>>>(n_right);
    scatter_kernel<<<eb, 256>>>(eidx, n_edges);

    // tensor-core projections
    const int blocksL = (n_left + TROWS - 1) / TROWS;
    const int blocksR = (n_right + TROWS - 1) / TROWS;
    proj_mma<<<blocksL + blocksR, 256, SM_PROJ>>>(left, right, b_left,
                                                  n_left, n_right, blocksL);

    // CSR edge stage: gather Lp only, registers for Rp/acc, no atomics
    edge_csr<<<(n_right + 7) / 8, 256>>>(eidx, ef, W_edge, scale_final,
                                         n_edges, n_right);

    // fused output MLP (Wf folded into Wc; deg from rowptr)
    out_mma<<<(n_right + TROWS - 1) / TROWS, 256, SM_OUT>>>(right, b_out1, b_out2,
                                                            (float*)d_out, n_right);
}

// round 15
// speedup vs baseline: 1.3885x; 1.3885x over previous
#include <cuda_runtime.h>
#include <cstdint>

#define EMB 128
#define ASTRIDE 132
#define TROWS 64
#define MAXNODES 100000
#define MAXEDGES 1048576

// Scratch (device globals: no allocations allowed in kernel_launch)
__device__ __align__(128) float g_Lp[MAXNODES * EMB];
__device__ __align__(128) float g_Rp[MAXNODES * EMB];
__device__ __align__(128) float g_acc[MAXNODES * EMB];
__device__ __align__(128) int g_cnt[MAXNODES];        // counts, then fill offsets
__device__ __align__(128) int g_rowptr[MAXNODES + 1];
__device__ __align__(128) int g_elist[MAXEDGES];
__device__ __align__(128) int g_psum[1024];           // per-block partial sums
__device__ __align__(128) float g_Wc[EMB * EMB];      // sp * (W1a @ Wf)
__device__ __align__(128) float g_bvec[EMB];          // sp * (W1a @ bf)
// fragment-packed hi-only tf32 weights: [m][(ks*16+nt)*32+lane] = {b0h,b1h}
// m: 0=W_left 1=W_right 2=Wc 3=W1b 4=W_out2
__device__ __align__(128) float2 g_frag[5][8192];
__device__ int g_is64;

// ---------------- helpers ----------------
__device__ __forceinline__ uint32_t tf32r(float v) {
    uint32_t r;
    asm("cvt.rna.tf32.f32 %0, %1;" : "=r"(r) : "f"(v));
    return r;
}
__device__ __forceinline__ void mma8(float* c, uint32_t a0, uint32_t a1,
                                     uint32_t a2, uint32_t a3,
                                     uint32_t b0, uint32_t b1) {
    asm volatile(
        "mma.sync.aligned.m16n8k8.row.col.f32.tf32.tf32.f32 "
        "{%0,%1,%2,%3}, {%4,%5,%6,%7}, {%8,%9}, {%0,%1,%2,%3};"
        : "+f"(c[0]), "+f"(c[1]), "+f"(c[2]), "+f"(c[3])
        : "r"(a0), "r"(a1), "r"(a2), "r"(a3), "r"(b0), "r"(b1));
}

// ---------------------------------------------------------------------------
// 64x128x128 2-pass compensated-TF32 GEMM (D = Ah@Bh + Al@Bh), 8 warps.
// ---------------------------------------------------------------------------
__device__ __forceinline__ void gemm64(const float* __restrict__ As,
                                       const float2* __restrict__ Bf,
                                       float acc[8][4], int rg, int ch, int lane) {
    const int g = lane >> 2, t = lane & 3;
    const float* r0 = As + (rg * 16 + g) * ASTRIDE;
    const float* r8 = r0 + 8 * ASTRIDE;
#pragma unroll
    for (int ks = 0; ks < 16; ks++) {
        const int k = ks * 8 + t;
        const float a0 = r0[k], a1 = r8[k], a2 = r0[k + 4], a3 = r8[k + 4];
        const uint32_t a0h = tf32r(a0), a1h = tf32r(a1);
        const uint32_t a2h = tf32r(a2), a3h = tf32r(a3);
        const uint32_t a0l = tf32r(a0 - __uint_as_float(a0h));
        const uint32_t a1l = tf32r(a1 - __uint_as_float(a1h));
        const uint32_t a2l = tf32r(a2 - __uint_as_float(a2h));
        const uint32_t a3l = tf32r(a3 - __uint_as_float(a3h));
        const float2* bp = Bf + ks * 512 + ch * 256 + lane;
#pragma unroll
        for (int nt = 0; nt < 8; nt++) {
            const float2 b = bp[nt * 32];
            const uint32_t b0h = __float_as_uint(b.x), b1h = __float_as_uint(b.y);
            mma8(acc[nt], a0h, a1h, a2h, a3h, b0h, b1h);
            mma8(acc[nt], a0l, a1l, a2l, a3l, b0h, b1h);
        }
    }
}

// stage TROWS rows of a row-major [n, 128] matrix into padded smem (zero-fill OOB)
__device__ __forceinline__ void stage_rows(const float* __restrict__ gptr, int row0,
                                           int n, float* As, int tid) {
    for (int i = tid; i < TROWS * 32; i += 256) {
        const int r = i >> 5, c4 = i & 31;
        float4 v = make_float4(0.f, 0.f, 0.f, 0.f);
        if (row0 + r < n)
            v = ((const float4*)(gptr + (size_t)(row0 + r) * EMB))[c4];
        *(float4*)(As + r * ASTRIDE + c4 * 4) = v;
    }
}

// ---------------------------------------------------------------------------
// prep1: detect idx width; zero g_cnt (FULL n_right range — graph-replay
// idempotence); Wc = sp*(W1a@Wf); bvec = sp*(W1a@bf).
// ---------------------------------------------------------------------------
__global__ void prep1_kernel(const float* __restrict__ Wf, const float* __restrict__ W1,
                             const float* __restrict__ bf, const float* __restrict__ sp_p,
                             const long long* __restrict__ eidx, int n_edges,
                             int n_right) {
    const int idx = blockIdx.x * blockDim.x + threadIdx.x;
    if (idx == 0) {
        int m = n_edges < 64 ? n_edges : 64;
        int ok = 1;
        for (int i = 0; i < m; i++) {
            long long v = eidx[i];
            if (v < 0 || v >= (1LL << 31)) { ok = 0; break; }
        }
        g_is64 = ok;
    }
    if (idx < n_right) g_cnt[idx] = 0;
    if (idx < EMB * EMB) {
        const int j = idx >> 7, k = idx & 127;
        float s = 0.f;
        for (int m = 0; m < EMB; m++)
            s = fmaf(W1[j * 2 * EMB + m], Wf[m * EMB + k], s);
        g_Wc[idx] = s * sp_p[0];
    }
    if (idx < EMB) {
        float s = 0.f;
        for (int m = 0; m < EMB; m++)
            s = fmaf(W1[idx * 2 * EMB + m], bf[m], s);
        g_bvec[idx] = s * sp_p[0];
    }
}

// ---------------------------------------------------------------------------
// prep2: pack fragment-ordered hi tf32 weights.
// ---------------------------------------------------------------------------
__global__ void prep2_kernel(const float* __restrict__ Wl, const float* __restrict__ Wr,
                             const float* __restrict__ W1, const float* __restrict__ W2) {
    const int idx = blockIdx.x * blockDim.x + threadIdx.x;
    if (idx >= 5 * 8192) return;
    const int m = idx >> 13, r = idx & 8191;
    const int lane = r & 31, nt = (r >> 5) & 15, ks = r >> 9;   // ks in [0,16)
    const int g = lane >> 2, t = lane & 3;
    const int n = nt * 8 + g, k0 = ks * 8 + t;

    const float* src; int L, off;
    switch (m) {
        case 0:  src = Wl;   L = EMB;     off = 0;   break;
        case 1:  src = Wr;   L = EMB;     off = 0;   break;
        case 2:  src = g_Wc; L = EMB;     off = 0;   break;
        case 3:  src = W1;   L = 2 * EMB; off = EMB; break;
        default: src = W2;   L = EMB;     off = 0;   break;
    }
    const float v0 = src[n * L + off + k0];
    const float v1 = src[n * L + off + k0 + 4];
    g_frag[m][r] = make_float2(__uint_as_float(tf32r(v0)),
                               __uint_as_float(tf32r(v1)));
}

// ---------------------------------------------------------------------------
// CSR build: histogram -> hierarchical scan (coalesced) -> scatter
// ---------------------------------------------------------------------------
__global__ void hist_kernel(const void* __restrict__ eidx_raw, int n_edges) {
    const int e = blockIdx.x * blockDim.x + threadIdx.x;
    if (e >= n_edges) return;
    const int d = g_is64 ? (int)((const long long*)eidx_raw)[n_edges + e]
                         : ((const int*)eidx_raw)[n_edges + e];
    atomicAdd(&g_cnt[d], 1);
}

// per-block sum of 256 counts (coalesced)
__global__ void scan_part(int n_right) {
    __shared__ int s[256];
    const int tid = threadIdx.x;
    const int i = blockIdx.x * 256 + tid;
    s[tid] = (i < n_right) ? g_cnt[i] : 0;
    __syncthreads();
#pragma unroll
    for (int ofs = 128; ofs > 0; ofs >>= 1) {
        if (tid < ofs) s[tid] += s[tid + ofs];
        __syncthreads();
    }
    if (tid == 0) g_psum[blockIdx.x] = s[0];
}

// single block: exclusive scan of block partials (nblocks <= 1024)
__global__ void scan_mid(int nblocks) {
    __shared__ int s[1024];
    const int tid = threadIdx.x;
    int v = (tid < nblocks) ? g_psum[tid] : 0;
    s[tid] = v;
    __syncthreads();
    for (int ofs = 1; ofs < 1024; ofs <<= 1) {
        int x = s[tid];
        int add = (tid >= ofs) ? s[tid - ofs] : 0;
        __syncthreads();
        s[tid] = x + add;
        __syncthreads();
    }
    if (tid < nblocks) g_psum[tid] = s[tid] - v;   // exclusive
}

// block-local exclusive scan + base -> rowptr + fill cursors (coalesced)
__global__ void scan_final(int n_right) {
    __shared__ int s[256];
    const int tid = threadIdx.x;
    const int i = blockIdx.x * 256 + tid;
    const int v = (i < n_right) ? g_cnt[i] : 0;
    s[tid] = v;
    __syncthreads();
#pragma unroll
    for (int ofs = 1; ofs < 256; ofs <<= 1) {
        int x = s[tid];
        int add = (tid >= ofs) ? s[tid - ofs] : 0;
        __syncthreads();
        s[tid] = x + add;
        __syncthreads();
    }
    const int base = g_psum[blockIdx.x];
    const int incl = s[tid];
    const int excl = incl - v;
    if (i < n_right) {
        g_rowptr[i] = base + excl;
        g_cnt[i] = base + excl;   // becomes fill cursor
        if (i == n_right - 1) g_rowptr[n_right] = base + incl;
    }
}

__global__ void scatter_kernel(const void* __restrict__ eidx_raw, int n_edges) {
    const int e = blockIdx.x * blockDim.x + threadIdx.x;
    if (e >= n_edges) return;
    const int d = g_is64 ? (int)((const long long*)eidx_raw)[n_edges + e]
                         : ((const int*)eidx_raw)[n_edges + e];
    const int pos = atomicAdd(&g_cnt[d], 1);
    g_elist[pos] = e;
}

// ---------------------------------------------------------------------------
// Tensor-core projections: Lp = left@WL^T + bL ; Rp = right@WR^T
// ---------------------------------------------------------------------------
__global__ __launch_bounds__(256) void proj_mma(
    const float* __restrict__ left, const float* __restrict__ right,
    const float* __restrict__ bL, int n_left, int n_right, int blocksL)
{
    extern __shared__ float sm[];
    float* As = sm;
    float* sBias = sm + TROWS * ASTRIDE;
    const int tid = threadIdx.x, warp = tid >> 5, lane = tid & 31;
    const int rg = warp >> 1, ch = warp & 1;

    const float* A; const float2* Bf; float* outp; int n, row0;
    if ((int)blockIdx.x < blocksL) {
        A = left;  Bf = g_frag[0]; outp = g_Lp; n = n_left;
        row0 = blockIdx.x * TROWS;
        if (tid < 128) sBias[tid] = bL[tid];
    } else {
        A = right; Bf = g_frag[1]; outp = g_Rp; n = n_right;
        row0 = (blockIdx.x - blocksL) * TROWS;
        if (tid < 128) sBias[tid] = 0.f;
    }
    stage_rows(A, row0, n, As, tid);
    __syncthreads();

    float acc[8][4];
#pragma unroll
    for (int nt = 0; nt < 8; nt++)
#pragma unroll
        for (int i = 0; i < 4; i++) acc[nt][i] = 0.f;

    gemm64(As, Bf, acc, rg, ch, lane);

    const int g = lane >> 2, t = lane & 3;
    const int r0 = row0 + rg * 16 + g, r1 = r0 + 8;
#pragma unroll
    for (int nt = 0; nt < 8; nt++) {
        const int c = (ch * 8 + nt) * 8 + 2 * t;
        if (r0 < n) {
            float2 o = make_float2(acc[nt][0] + sBias[c], acc[nt][1] + sBias[c + 1]);
            *(float2*)(outp + (size_t)r0 * EMB + c) = o;
        }
        if (r1 < n) {
            float2 o = make_float2(acc[nt][2] + sBias[c], acc[nt][3] + sBias[c + 1]);
            *(float2*)(outp + (size_t)r1 * EMB + c) = o;
        }
    }
}

// ---------------------------------------------------------------------------
// CSR edge stage: one warp per destination d. Rp[d] + accumulator live in
// registers; only Lp[s] is gathered (51 MB, L2-resident). Plain store to
// g_acc[d] — no float atomics, no zero-init needed.
// ---------------------------------------------------------------------------
__global__ __launch_bounds__(256) void edge_csr(
    const void* __restrict__ eidx_raw, const float* __restrict__ ef,
    const float* __restrict__ wedge, const float* __restrict__ scale_p,
    int n_edges, int n_right)
{
    const int warp = threadIdx.x >> 5, lane = threadIdx.x & 31;
    const int d = blockIdx.x * 8 + warp;
    if (d >= n_right) return;

    const int beg = g_rowptr[d];
    const int end = g_rowptr[d + 1];
    const float scale = scale_p[0];
    const float4 we = ((const float4*)wedge)[lane];
    const float4 r = ((const float4*)(g_Rp + (size_t)d * EMB))[lane];
    const int is64 = g_is64;
    const long long* __restrict__ e64 = (const long long*)eidx_raw;
    const int* __restrict__ e32 = (const int*)eidx_raw;

    float4 a = make_float4(0.f, 0.f, 0.f, 0.f);
    for (int p = beg; p < end; p++) {
        const int e = g_elist[p];
        const int s = is64 ? (int)e64[e] : e32[e];
        const float fe = ef[e];
        const float4 l = ((const float4*)(g_Lp + (size_t)s * EMB))[lane];
        a.x += fmaxf(fmaf(fe, we.x, l.x + r.x) * scale, 0.f);
        a.y += fmaxf(fmaf(fe, we.y, l.y + r.y) * scale, 0.f);
        a.z += fmaxf(fmaf(fe, we.z, l.z + r.z) * scale, 0.f);
        a.w += fmaxf(fmaf(fe, we.w, l.w + r.w) * scale, 0.f);
    }
    ((float4*)(g_acc + (size_t)d * EMB))[lane] = a;
}

// ---------------------------------------------------------------------------
// Fused output: u = relu(acc@Wc^T + deg*bvec + right@W1b^T + b1);
//               out = u@W2^T + b2.   (Wf folded into Wc; deg from rowptr.)
// ---------------------------------------------------------------------------
__global__ __launch_bounds__(256) void out_mma(
    const float* __restrict__ right, const float* __restrict__ b1,
    const float* __restrict__ b2, float* __restrict__ out, int n_right)
{
    extern __shared__ float sm[];
    float* As = sm;                          // acc tile, later u tile
    float* Rs = sm + TROWS * ASTRIDE;        // right tile
    float* sBv = sm + 2 * TROWS * ASTRIDE;
    float* sB1 = sBv + 128;
    float* sB2 = sB1 + 128;
    const int tid = threadIdx.x, warp = tid >> 5, lane = tid & 31;
    const int rg = warp >> 1, ch = warp & 1;
    const int row0 = blockIdx.x * TROWS;

    if (tid < 128) {
        sBv[tid] = g_bvec[tid];
        sB1[tid] = b1[tid];
        sB2[tid] = b2[tid];
    }
    stage_rows(g_acc, row0, n_right, As, tid);
    stage_rows(right, row0, n_right, Rs, tid);
    __syncthreads();

    float acc[8][4];
#pragma unroll
    for (int nt = 0; nt < 8; nt++)
#pragma unroll
        for (int i = 0; i < 4; i++) acc[nt][i] = 0.f;

    gemm64(As, g_frag[2], acc, rg, ch, lane);   // acc_tile @ Wc^T
    gemm64(Rs, g_frag[3], acc, rg, ch, lane);   // + right @ W1b^T

    const int g = lane >> 2, t = lane & 3;
    const int sr0 = rg * 16 + g, sr1 = sr0 + 8;
    float d0 = 0.f, d1 = 0.f;
    if (row0 + sr0 < n_right)
        d0 = (float)(g_rowptr[row0 + sr0 + 1] - g_rowptr[row0 + sr0]);
    if (row0 + sr1 < n_right)
        d1 = (float)(g_rowptr[row0 + sr1 + 1] - g_rowptr[row0 + sr1]);
    __syncthreads();   // everyone done reading As

    // u = relu(acc + deg*bvec + b1) -> As
#pragma unroll
    for (int nt = 0; nt < 8; nt++) {
        const int c = (ch * 8 + nt) * 8 + 2 * t;
        As[sr0 * ASTRIDE + c]     = fmaxf(acc[nt][0] + d0 * sBv[c]     + sB1[c],     0.f);
        As[sr0 * ASTRIDE + c + 1] = fmaxf(acc[nt][1] + d0 * sBv[c + 1] + sB1[c + 1], 0.f);
        As[sr1 * ASTRIDE + c]     = fmaxf(acc[nt][2] + d1 * sBv[c]     + sB1[c],     0.f);
        As[sr1 * ASTRIDE + c + 1] = fmaxf(acc[nt][3] + d1 * sBv[c + 1] + sB1[c + 1], 0.f);
    }
    __syncthreads();

    // u @ W2^T
#pragma unroll
    for (int nt = 0; nt < 8; nt++)
#pragma unroll
        for (int i = 0; i < 4; i++) acc[nt][i] = 0.f;

    gemm64(As, g_frag[4], acc, rg, ch, lane);

    const int r0g = row0 + sr0, r1g = row0 + sr1;
#pragma unroll
    for (int nt = 0; nt < 8; nt++) {
        const int c = (ch * 8 + nt) * 8 + 2 * t;
        if (r0g < n_right) {
            float2 o = make_float2(acc[nt][0] + sB2[c], acc[nt][1] + sB2[c + 1]);
            *(float2*)(out + (size_t)r0g * EMB + c) = o;
        }
        if (r1g < n_right) {
            float2 o = make_float2(acc[nt][2] + sB2[c], acc[nt][3] + sB2[c + 1]);
            *(float2*)(out + (size_t)r1g * EMB + c) = o;
        }
    }
}

// ---------------------------------------------------------------------------
extern "C" void kernel_launch(void* const* d_in, const int* in_sizes, int n_in,
                              void* d_out, int out_size)
{
    const float* left   = (const float*)d_in[0];
    const void*  eidx   = d_in[1];
    const float* ef     = (const float*)d_in[2];
    const float* right  = (const float*)d_in[3];
    // d_in[4] = scatter_out_size scalar (derived from right_features instead)
    const float* W_left      = (const float*)d_in[5];
    const float* b_left      = (const float*)d_in[6];
    const float* W_edge      = (const float*)d_in[7];
    const float* W_right     = (const float*)d_in[8];
    const float* scale_final = (const float*)d_in[9];
    const float* W_final     = (const float*)d_in[10];
    const float* b_final     = (const float*)d_in[11];
    const float* scale_post  = (const float*)d_in[12];
    const float* W_out1      = (const float*)d_in[13];
    const float* b_out1      = (const float*)d_in[14];
    const float* W_out2      = (const float*)d_in[15];
    const float* b_out2      = (const float*)d_in[16];

    const int n_left  = in_sizes[0] / EMB;
    const int n_edges = in_sizes[2];          // edge_features count (EDGE_FEAT=1)
    const int n_right = in_sizes[3] / EMB;

    const int SM_PROJ = (TROWS * ASTRIDE + 128) * (int)sizeof(float);
    const int SM_OUT  = (2 * TROWS * ASTRIDE + 3 * 128) * (int)sizeof(float);
    cudaFuncSetAttribute(proj_mma, cudaFuncAttributeMaxDynamicSharedMemorySize, SM_PROJ);
    cudaFuncSetAttribute(out_mma,  cudaFuncAttributeMaxDynamicSharedMemorySize, SM_OUT);

    const int eb = (n_edges + 255) / 256;
    const int nb = (n_right + 255) / 256;     // scan blocks (<= 1024)

    // prep: idx width, zero counts (FULL range), folded weights, fragments
    const int prep1_span = (n_right > EMB * EMB) ? n_right : EMB * EMB;
    prep1_kernel<<<(prep1_span + 255) / 256, 256>>>(W_final, W_out1, b_final,
                                                    scale_post,
                                                    (const long long*)eidx,
                                                    n_edges, n_right);
    prep2_kernel<<<(5 * 8192 + 255) / 256, 256>>>(W_left, W_right, W_out1, W_out2);

    // CSR build (hierarchical coalesced scan)
    hist_kernel<<<eb, 256>>>(eidx, n_edges);
    scan_part<<<nb, 256>>>(n_right);
    scan_mid<<<1, 1024>>>(nb);
    scan_final<<<nb, 256>>>(n_right);
    scatter_kernel<<<eb, 256>>>(eidx, n_edges);

    // tensor-core projections
    const int blocksL = (n_left + TROWS - 1) / TROWS;
    const int blocksR = (n_right + TROWS - 1) / TROWS;
    proj_mma<<<blocksL + blocksR, 256, SM_PROJ>>>(left, right, b_left,
                                                  n_left, n_right, blocksL);

    // CSR edge stage: gather Lp only, registers for Rp/acc, no atomics
    edge_csr<<<(n_right + 7) / 8, 256>>>(eidx, ef, W_edge, scale_final,
                                         n_edges, n_right);

    // fused output MLP (Wf folded into Wc; deg from rowptr)
    out_mma<<<(n_right + TROWS - 1) / TROWS, 256, SM_OUT>>>(right, b_out1, b_out2,
                                                            (float*)d_out, n_right);
}